// round 16
// baseline (speedup 1.0000x reference)
#include <cuda_runtime.h>
#include <float.h>

// NormmaxBisect, alpha = 1.5, n_iter = 50, d = 2048.
// p = max(x - tau, 0)^2 ; p^alpha = max(x - tau, 0)^3.
// Only elements with x > max-1 can be nonzero. Output = zero-fill + scatter.
// tau* solved by Newton on f(tau) = sum c^3 - 1 (convex, decreasing; started
// on the f>=0 side => monotone quadratic convergence, warp-uniform early
// exit); lands within ~1 ulp of the reference's 50-step fp32 bisection.
// EXACT round-14 structure (measured best, 160.9us). Single delta: the two
// read-once row loads use __ldcg (L2-only, no L1 allocate) -- the row is never
// re-read, so L1 allocation is pure overhead on the L1TEX pipeline.

constexpr int   D       = 2048;
constexpr int   THREADS = 256;
constexpr int   CAP     = 128;                        // >> E[#candidates] ~ 23
constexpr float TAU_HI_OFF = 0.022097086912079612f;   // (1/2048)^0.5

__global__ void __launch_bounds__(THREADS)
normmax_kernel(const float* __restrict__ X, float* __restrict__ Out)
{
    __shared__ float s_cand[CAP];
    __shared__ int   s_pos[CAP];
    __shared__ float s_red[THREADS / 32];
    __shared__ int   s_cnt;

    const size_t base = (size_t)blockIdx.x * D;
    const float4* __restrict__ xin  = reinterpret_cast<const float4*>(X + base);
    float4* __restrict__       xout = reinterpret_cast<float4*>(Out + base);

    const int t    = threadIdx.x;
    const int lane = t & 31;
    const int wid  = t >> 5;
    if (t == 0) s_cnt = 0;

    // ---- Load 8 elems/thread (L2-only: read-once stream), zero-fill early ----
    float4 v0 = __ldcg(xin + t);
    float4 v1 = __ldcg(xin + t + THREADS);
    const float4 z4 = make_float4(0.f, 0.f, 0.f, 0.f);
    xout[t]           = z4;
    xout[t + THREADS] = z4;

    float x0 = v0.x, x1 = v0.y, x2 = v0.z, x3 = v0.w;
    float x4 = v1.x, x5 = v1.y, x6 = v1.z, x7 = v1.w;

    float m = fmaxf(fmaxf(fmaxf(x0, x1), fmaxf(x2, x3)),
                    fmaxf(fmaxf(x4, x5), fmaxf(x6, x7)));
#pragma unroll
    for (int o = 16; o; o >>= 1)
        m = fmaxf(m, __shfl_xor_sync(0xffffffffu, m, o));
    if (lane == 0) s_red[wid] = m;
    __syncthreads();

    float maxval = s_red[0];
#pragma unroll
    for (int w = 1; w < THREADS / 32; ++w) maxval = fmaxf(maxval, s_red[w]);
    const float thresh = maxval - 1.0f;

    // ---- Gather candidates: per-thread bitmask, one atomic per hit-thread ----
    unsigned mm = 0;
    mm |= (x0 > thresh) ? 1u   : 0u;
    mm |= (x1 > thresh) ? 2u   : 0u;
    mm |= (x2 > thresh) ? 4u   : 0u;
    mm |= (x3 > thresh) ? 8u   : 0u;
    mm |= (x4 > thresh) ? 16u  : 0u;
    mm |= (x5 > thresh) ? 32u  : 0u;
    mm |= (x6 > thresh) ? 64u  : 0u;
    mm |= (x7 > thresh) ? 128u : 0u;
    if (mm) {   // ~5% of threads
        int p = atomicAdd(&s_cnt, __popc(mm));
        float xv[8] = {x0, x1, x2, x3, x4, x5, x6, x7};
#pragma unroll
        for (int i = 0; i < 8; ++i) {
            if ((mm >> i) & 1) {
                if (p < CAP) {
                    s_cand[p] = xv[i];
                    // element index: float4 slot (t + (i>>2)*THREADS), component i&3
                    s_pos[p]  = 4 * t + (i >> 2) * (4 * THREADS) + (i & 3);
                }
                ++p;
            }
        }
    }
    __syncthreads();
    const int n = s_cnt;

    // Only one warp continues; the rest retire (their zero-fill stores are
    // ordered before the scatter by the barrier above).
    if (wid != (int)(blockIdx.x & (unsigned)(THREADS / 32 - 1))) return;

    if (n <= CAP) {
        // ---- Newton on f(tau) = sum c^3 - 1, lane-parallel over <=128 cands ----
        const float SENT = -1.0e30f;   // contributes exactly 0 through fmaxf
        float cv0 = (lane      < n) ? s_cand[lane]      : SENT;
        float cv1 = (lane + 32 < n) ? s_cand[lane + 32] : SENT;
        float cv2 = (lane + 64 < n) ? s_cand[lane + 64] : SENT;
        float cv3 = (lane + 96 < n) ? s_cand[lane + 96] : SENT;

        const float tau_hi = maxval - TAU_HI_OFF;   // f(tau_hi) < 0 always
        float tau = thresh;                          // f(thresh) >= 0

        // Converged-iteration state: S = sum c^2 and per-lane q at the same
        // tau the loop settles on (bit-identical to a post-loop recompute on
        // the early-exit path, which is the one that fires in practice).
        float S = 1.0f, Q0 = 0.f, Q1 = 0.f, Q2 = 0.f, Q3 = 0.f;

#pragma unroll 1
        for (int it = 0; it < 8; ++it) {
            float c0 = fmaxf(cv0 - tau, 0.f), q0 = c0 * c0;
            float c1 = fmaxf(cv1 - tau, 0.f), q1 = c1 * c1;
            float c2 = fmaxf(cv2 - tau, 0.f), q2 = c2 * c2;
            float c3 = fmaxf(cv3 - tau, 0.f), q3 = c3 * c3;
            float a = (q0 + q1) + (q2 + q3);                              // sum c^2
            float b = fmaf(q0, c0, fmaf(q1, c1, fmaf(q2, c2, q3 * c3))); // sum c^3
#pragma unroll
            for (int o = 16; o; o >>= 1) {  // two independent chains, pipelined
                a += __shfl_xor_sync(0xffffffffu, a, o);
                b += __shfl_xor_sync(0xffffffffu, b, o);
            }
            // Save state at THIS tau (a >= (maxval-tau)^2 >= TAU_HI_OFF^2 > 0).
            S = a; Q0 = q0; Q1 = q1; Q2 = q2; Q3 = q3;
            // f = b - 1, f' = -3a
            float nt = tau + (b - 1.0f) / (3.0f * a);
            nt = fminf(fmaxf(nt, thresh), tau_hi);
            if (nt == tau) break;           // converged (warp-uniform: a,b are
            tau = nt;                       // bit-identical on all lanes)
        }

        // ---- Normalize + scatter straight from the converged registers ----
        const float invS = 1.0f / S;
        // Q == 0 (SENT slots or clamped candidates) -> stays zero-filled.
        if (Q0 > 0.f) Out[base + s_pos[lane]]      = Q0 * invS;
        if (Q1 > 0.f) Out[base + s_pos[lane + 32]] = Q1 * invS;
        if (Q2 > 0.f) Out[base + s_pos[lane + 64]] = Q2 * invS;
        if (Q3 > 0.f) Out[base + s_pos[lane + 96]] = Q3 * invS;
    } else {
        // ---- Dense fallback (statistically never): exact reference bisection,
        //      single warp, row re-read through L1/L2. ----
        float tau_lo = thresh;
        float dm     = (maxval - TAU_HI_OFF) - tau_lo;
        float tau_m  = tau_lo;
        for (int it = 0; it < 50; ++it) {
            dm *= 0.5f;
            tau_m = tau_lo + dm;
            if (tau_m == tau_lo) break;
            float s = 0.f;
            for (int j = lane; j < D; j += 32) {
                float c = fmaxf(X[base + j] - tau_m, 0.f);
                s = fmaf(c * c, c, s);
            }
#pragma unroll
            for (int o = 16; o; o >>= 1) s += __shfl_xor_sync(0xffffffffu, s, o);
            if (s >= 1.0f) tau_lo = tau_m;
        }
        float S = 0.f;
        for (int j = lane; j < D; j += 32) {
            float c = fmaxf(X[base + j] - tau_m, 0.f);
            S = fmaf(c, c, S);
        }
#pragma unroll
        for (int o = 16; o; o >>= 1) S += __shfl_xor_sync(0xffffffffu, S, o);
        const float invS = 1.0f / S;
        for (int j = lane; j < D; j += 32) {
            float c = fmaxf(X[base + j] - tau_m, 0.f);
            Out[base + j] = c * c * invS;
        }
    }
}

extern "C" void kernel_launch(void* const* d_in, const int* in_sizes, int n_in,
                              void* d_out, int out_size) {
    const float* X = (const float*)d_in[0];
    float* Out = (float*)d_out;
    int nrows = out_size / D;
    normmax_kernel<<<nrows, THREADS>>>(X, Out);
}

// round 17
// speedup vs baseline: 1.0175x; 1.0175x over previous
#include <cuda_runtime.h>
#include <float.h>

// NormmaxBisect, alpha = 1.5, n_iter = 50, d = 2048.   [FINAL — round-14 optimum]
// p = max(x - tau, 0)^2 ; p^alpha = max(x - tau, 0)^3.
// Only elements with x > max-1 can be nonzero. Output = zero-fill + scatter.
// tau* solved by Newton on f(tau) = sum c^3 - 1 (convex, decreasing; started
// on the f>=0 side => monotone quadratic convergence, warp-uniform early
// exit); lands within ~1 ulp of the reference's 50-step fp32 bisection.
// The converged iteration's a (= sum c^2) and q0..q3 are reused for the final
// normalization and scatter (no post-loop recompute / extra butterfly).
//
// Measured: 160.9us wall, HBM 6.32 TB/s = ~98% of the ~6.5 TB/s mixed-stream
// practical ceiling measured on this chip (tail-free control kernel, R10).

constexpr int   D       = 2048;
constexpr int   THREADS = 256;
constexpr int   CAP     = 128;                        // >> E[#candidates] ~ 23
constexpr float TAU_HI_OFF = 0.022097086912079612f;   // (1/2048)^0.5

__global__ void __launch_bounds__(THREADS)
normmax_kernel(const float* __restrict__ X, float* __restrict__ Out)
{
    __shared__ float s_cand[CAP];
    __shared__ int   s_pos[CAP];
    __shared__ float s_red[THREADS / 32];
    __shared__ int   s_cnt;

    const size_t base = (size_t)blockIdx.x * D;
    const float4* __restrict__ xin  = reinterpret_cast<const float4*>(X + base);
    float4* __restrict__       xout = reinterpret_cast<float4*>(Out + base);

    const int t    = threadIdx.x;
    const int lane = t & 31;
    const int wid  = t >> 5;
    if (t == 0) s_cnt = 0;

    // ---- Load 8 elems/thread, zero-fill output early, block max ----
    float4 v0 = xin[t];
    float4 v1 = xin[t + THREADS];
    const float4 z4 = make_float4(0.f, 0.f, 0.f, 0.f);
    xout[t]           = z4;
    xout[t + THREADS] = z4;

    float x0 = v0.x, x1 = v0.y, x2 = v0.z, x3 = v0.w;
    float x4 = v1.x, x5 = v1.y, x6 = v1.z, x7 = v1.w;

    float m = fmaxf(fmaxf(fmaxf(x0, x1), fmaxf(x2, x3)),
                    fmaxf(fmaxf(x4, x5), fmaxf(x6, x7)));
#pragma unroll
    for (int o = 16; o; o >>= 1)
        m = fmaxf(m, __shfl_xor_sync(0xffffffffu, m, o));
    if (lane == 0) s_red[wid] = m;
    __syncthreads();

    float maxval = s_red[0];
#pragma unroll
    for (int w = 1; w < THREADS / 32; ++w) maxval = fmaxf(maxval, s_red[w]);
    const float thresh = maxval - 1.0f;

    // ---- Gather candidates: per-thread bitmask, one atomic per hit-thread ----
    unsigned mm = 0;
    mm |= (x0 > thresh) ? 1u   : 0u;
    mm |= (x1 > thresh) ? 2u   : 0u;
    mm |= (x2 > thresh) ? 4u   : 0u;
    mm |= (x3 > thresh) ? 8u   : 0u;
    mm |= (x4 > thresh) ? 16u  : 0u;
    mm |= (x5 > thresh) ? 32u  : 0u;
    mm |= (x6 > thresh) ? 64u  : 0u;
    mm |= (x7 > thresh) ? 128u : 0u;
    if (mm) {   // ~5% of threads
        int p = atomicAdd(&s_cnt, __popc(mm));
        float xv[8] = {x0, x1, x2, x3, x4, x5, x6, x7};
#pragma unroll
        for (int i = 0; i < 8; ++i) {
            if ((mm >> i) & 1) {
                if (p < CAP) {
                    s_cand[p] = xv[i];
                    // element index: float4 slot (t + (i>>2)*THREADS), component i&3
                    s_pos[p]  = 4 * t + (i >> 2) * (4 * THREADS) + (i & 3);
                }
                ++p;
            }
        }
    }
    __syncthreads();
    const int n = s_cnt;

    // Only one warp continues; the rest retire (their zero-fill stores are
    // ordered before the scatter by the barrier above).
    if (wid != (int)(blockIdx.x & (unsigned)(THREADS / 32 - 1))) return;

    if (n <= CAP) {
        // ---- Newton on f(tau) = sum c^3 - 1, lane-parallel over <=128 cands ----
        const float SENT = -1.0e30f;   // contributes exactly 0 through fmaxf
        float cv0 = (lane      < n) ? s_cand[lane]      : SENT;
        float cv1 = (lane + 32 < n) ? s_cand[lane + 32] : SENT;
        float cv2 = (lane + 64 < n) ? s_cand[lane + 64] : SENT;
        float cv3 = (lane + 96 < n) ? s_cand[lane + 96] : SENT;

        const float tau_hi = maxval - TAU_HI_OFF;   // f(tau_hi) < 0 always
        float tau = thresh;                          // f(thresh) >= 0

        // Converged-iteration state: S = sum c^2 and per-lane q at the same
        // tau the loop settles on (bit-identical to a post-loop recompute on
        // the early-exit path, which is the one that fires in practice).
        float S = 1.0f, Q0 = 0.f, Q1 = 0.f, Q2 = 0.f, Q3 = 0.f;

#pragma unroll 1
        for (int it = 0; it < 8; ++it) {
            float c0 = fmaxf(cv0 - tau, 0.f), q0 = c0 * c0;
            float c1 = fmaxf(cv1 - tau, 0.f), q1 = c1 * c1;
            float c2 = fmaxf(cv2 - tau, 0.f), q2 = c2 * c2;
            float c3 = fmaxf(cv3 - tau, 0.f), q3 = c3 * c3;
            float a = (q0 + q1) + (q2 + q3);                              // sum c^2
            float b = fmaf(q0, c0, fmaf(q1, c1, fmaf(q2, c2, q3 * c3))); // sum c^3
#pragma unroll
            for (int o = 16; o; o >>= 1) {  // two independent chains, pipelined
                a += __shfl_xor_sync(0xffffffffu, a, o);
                b += __shfl_xor_sync(0xffffffffu, b, o);
            }
            // Save state at THIS tau (a >= (maxval-tau)^2 >= TAU_HI_OFF^2 > 0).
            S = a; Q0 = q0; Q1 = q1; Q2 = q2; Q3 = q3;
            // f = b - 1, f' = -3a
            float nt = tau + (b - 1.0f) / (3.0f * a);
            nt = fminf(fmaxf(nt, thresh), tau_hi);
            if (nt == tau) break;           // converged (warp-uniform: a,b are
            tau = nt;                       // bit-identical on all lanes)
        }

        // ---- Normalize + scatter straight from the converged registers ----
        const float invS = 1.0f / S;
        // Q == 0 (SENT slots or clamped candidates) -> stays zero-filled.
        if (Q0 > 0.f) Out[base + s_pos[lane]]      = Q0 * invS;
        if (Q1 > 0.f) Out[base + s_pos[lane + 32]] = Q1 * invS;
        if (Q2 > 0.f) Out[base + s_pos[lane + 64]] = Q2 * invS;
        if (Q3 > 0.f) Out[base + s_pos[lane + 96]] = Q3 * invS;
    } else {
        // ---- Dense fallback (statistically never): exact reference bisection,
        //      single warp, row re-read through L1/L2. ----
        float tau_lo = thresh;
        float dm     = (maxval - TAU_HI_OFF) - tau_lo;
        float tau_m  = tau_lo;
        for (int it = 0; it < 50; ++it) {
            dm *= 0.5f;
            tau_m = tau_lo + dm;
            if (tau_m == tau_lo) break;
            float s = 0.f;
            for (int j = lane; j < D; j += 32) {
                float c = fmaxf(X[base + j] - tau_m, 0.f);
                s = fmaf(c * c, c, s);
            }
#pragma unroll
            for (int o = 16; o; o >>= 1) s += __shfl_xor_sync(0xffffffffu, s, o);
            if (s >= 1.0f) tau_lo = tau_m;
        }
        float S = 0.f;
        for (int j = lane; j < D; j += 32) {
            float c = fmaxf(X[base + j] - tau_m, 0.f);
            S = fmaf(c, c, S);
        }
#pragma unroll
        for (int o = 16; o; o >>= 1) S += __shfl_xor_sync(0xffffffffu, S, o);
        const float invS = 1.0f / S;
        for (int j = lane; j < D; j += 32) {
            float c = fmaxf(X[base + j] - tau_m, 0.f);
            Out[base + j] = c * c * invS;
        }
    }
}

extern "C" void kernel_launch(void* const* d_in, const int* in_sizes, int n_in,
                              void* d_out, int out_size) {
    const float* X = (const float*)d_in[0];
    float* Out = (float*)d_out;
    int nrows = out_size / D;
    normmax_kernel<<<nrows, THREADS>>>(X, Out);
}